// round 2
// baseline (speedup 1.0000x reference)
#include <cuda_runtime.h>
#include <cuda_bf16.h>
#include <cstdint>

// ============================================================================
// out[4096,4096] = x @ W^T + b  (fp32).
// fp32 -> bf16 hi/lo split; 3-product warp-MMA (mma.sync m16n8k16 bf16) GEMM.
// Baseline sm_103 target: NO tcgen05 (harness compiles non-'a' PTX).
// ============================================================================

#define DIM 4096
#define BM 128
#define BN 128
#define BK 32
#define NKT (DIM / BK)          // 128 k-tiles
#define THREADS 256
#define STAGES 4

// per-stage smem: Ah|Al|Bh|Bl, each 128 rows x 32 bf16 (64B rows) = 8KB
#define STAGE_BYTES 32768
#define OFF_AH 0
#define OFF_AL 8192
#define OFF_BH 16384
#define OFF_BL 24576
#define SM_BIAS 0               // 128 floats
#define SM_TILES 1024
#define SMEM_TOTAL (SM_TILES + STAGES * STAGE_BYTES)   // 132096

// ---------------------------------------------------------------------------
// Scratch: bf16 hi/lo splits of x and W
// ---------------------------------------------------------------------------
__device__ __align__(256) __nv_bfloat16 g_xh[(size_t)DIM * DIM];
__device__ __align__(256) __nv_bfloat16 g_xl[(size_t)DIM * DIM];
__device__ __align__(256) __nv_bfloat16 g_wh[(size_t)DIM * DIM];
__device__ __align__(256) __nv_bfloat16 g_wl[(size_t)DIM * DIM];

// ---------------------------------------------------------------------------
// Helpers
// ---------------------------------------------------------------------------
static __device__ __forceinline__ uint32_t smem_u32(const void* p) {
    uint32_t a;
    asm("{ .reg .u64 t; cvta.to.shared.u64 t, %1; cvt.u32.u64 %0, t; }"
        : "=r"(a) : "l"(p));
    return a;
}

static __device__ __forceinline__ void cp16(uint32_t s, const void* g) {
    asm volatile("cp.async.cg.shared.global [%0], [%1], 16;" :: "r"(s), "l"(g));
}

static __device__ __forceinline__ void ldsm4(uint32_t* r, uint32_t a) {
    asm volatile("ldmatrix.sync.aligned.m8n8.x4.shared.b16 {%0,%1,%2,%3}, [%4];"
                 : "=r"(r[0]), "=r"(r[1]), "=r"(r[2]), "=r"(r[3]) : "r"(a));
}

static __device__ __forceinline__ void mma16816(float* c, const uint32_t* a,
                                                const uint32_t* b) {
    asm volatile(
        "mma.sync.aligned.m16n8k16.row.col.f32.bf16.bf16.f32 "
        "{%0,%1,%2,%3}, {%4,%5,%6,%7}, {%8,%9}, {%0,%1,%2,%3};"
        : "+f"(c[0]), "+f"(c[1]), "+f"(c[2]), "+f"(c[3])
        : "r"(a[0]), "r"(a[1]), "r"(a[2]), "r"(a[3]), "r"(b[0]), "r"(b[1]));
}

// ---------------------------------------------------------------------------
// Split kernel: fp32 -> bf16 hi + bf16 lo residual
// ---------------------------------------------------------------------------
__global__ __launch_bounds__(256) void split_kernel(const float* __restrict__ src,
                                                    int which) {
    __nv_bfloat16* hi = which ? g_wh : g_xh;
    __nv_bfloat16* lo = which ? g_wl : g_xl;
    size_t i = ((size_t)blockIdx.x * blockDim.x + threadIdx.x) * 4;
    float4 v = *reinterpret_cast<const float4*>(src + i);
    float vv[4] = {v.x, v.y, v.z, v.w};
    uint32_t h[4], l[4];
#pragma unroll
    for (int j = 0; j < 4; ++j) {
        __nv_bfloat16 hb = __float2bfloat16_rn(vv[j]);
        float r = vv[j] - __bfloat162float(hb);
        __nv_bfloat16 lb = __float2bfloat16_rn(r);
        h[j] = (uint32_t)__bfloat16_as_ushort(hb);
        l[j] = (uint32_t)__bfloat16_as_ushort(lb);
    }
    *reinterpret_cast<uint2*>(hi + i) = make_uint2(h[0] | (h[1] << 16), h[2] | (h[3] << 16));
    *reinterpret_cast<uint2*>(lo + i) = make_uint2(l[0] | (l[1] << 16), l[2] | (l[3] << 16));
}

// ---------------------------------------------------------------------------
// Stage loader: 8 cp.async(16B) per thread. Swizzle: chunk c at row r stored
// at r*64 + ((c ^ ((r>>1)&3))<<4)  -> conflict-free stores AND ldmatrix reads.
// ---------------------------------------------------------------------------
static __device__ __forceinline__ void load_stage(uint32_t sb, int stage, int kt,
                                                  int tm, int tn, int tid) {
    uint32_t st = sb + SM_TILES + stage * STAGE_BYTES;
    const uint32_t k0 = (uint32_t)kt * BK;
#pragma unroll
    for (int i = 0; i < 2; ++i) {
        int c = i * 256 + tid;          // 512 chunks: (row 0..127) x (chunk 0..3)
        int r = c >> 2, cc = c & 3;
        uint32_t so = (uint32_t)r * 64 + (uint32_t)((cc ^ ((r >> 1) & 3)) << 4);
        size_t gA = (size_t)(tm * BM + r) * DIM + k0 + cc * 8;
        size_t gB = (size_t)(tn * BN + r) * DIM + k0 + cc * 8;
        cp16(st + OFF_AH + so, g_xh + gA);
        cp16(st + OFF_AL + so, g_xl + gA);
        cp16(st + OFF_BH + so, g_wh + gB);
        cp16(st + OFF_BL + so, g_wl + gB);
    }
}

// ---------------------------------------------------------------------------
// GEMM: D(128x128) += Ah*Bh + Ah*Bl + Al*Bh over K, then +bias.
// 8 warps: wm = wid&1 (2 x 64 rows), wn = wid>>1 (4 x 32 cols).
// ---------------------------------------------------------------------------
__global__ __launch_bounds__(THREADS, 1) void gemm_kernel(const float* __restrict__ bias,
                                                          float* __restrict__ out) {
    extern __shared__ __align__(1024) char smem[];
    uint32_t sb = smem_u32(smem);
    const int tid = threadIdx.x;
    const int lane = tid & 31, wid = tid >> 5;
    const int wm = wid & 1, wn = wid >> 1;

    // panel raster: 4 panels of (8 tm x 32 tn) = 256 CTAs; wave fits in L2
    const int pid = blockIdx.x;
    const int panel = pid >> 8;
    const int ip = pid & 255;
    const int tm = panel * 8 + (ip & 7);
    const int tn = ip >> 3;

    if (tid < BN)
        reinterpret_cast<float*>(smem + SM_BIAS)[tid] = bias[tn * BN + tid];

    // per-lane ldmatrix address components
    uint32_t aoff[4], asw[4];
#pragma unroll
    for (int mt = 0; mt < 4; ++mt) {
        int r = wm * 64 + mt * 16 + (lane & 15);
        aoff[mt] = (uint32_t)r * 64;
        asw[mt] = (uint32_t)((r >> 1) & 3);
    }
    uint32_t boff[2], bsw[2];
#pragma unroll
    for (int jj = 0; jj < 2; ++jj) {
        int r = wn * 32 + jj * 16 + ((lane >> 4) & 1) * 8 + (lane & 7);
        boff[jj] = (uint32_t)r * 64;
        bsw[jj] = (uint32_t)((r >> 1) & 3);
    }
    const uint32_t cAsel = (uint32_t)(lane >> 4);        // A chunk select
    const uint32_t cBsel = (uint32_t)((lane >> 3) & 1);  // B chunk select

    float acc[4][4][4];
#pragma unroll
    for (int mt = 0; mt < 4; ++mt)
#pragma unroll
        for (int nt = 0; nt < 4; ++nt)
#pragma unroll
            for (int k = 0; k < 4; ++k) acc[mt][nt][k] = 0.f;

    // prologue: 3 stages in flight
#pragma unroll
    for (int s = 0; s < STAGES - 1; ++s) {
        load_stage(sb, s, s, tm, tn, tid);
        asm volatile("cp.async.commit_group;");
    }

    for (int t = 0; t < NKT; ++t) {
        asm volatile("cp.async.wait_group 2;");
        __syncthreads();

        if (t + STAGES - 1 < NKT)
            load_stage(sb, (t + STAGES - 1) & (STAGES - 1), t + STAGES - 1, tm, tn, tid);
        asm volatile("cp.async.commit_group;");   // empty group ok -> uniform counting

        const uint32_t stg = sb + SM_TILES + (uint32_t)(t & (STAGES - 1)) * STAGE_BYTES;
#pragma unroll
        for (int s = 0; s < 2; ++s) {             // two k16 steps per BK=32
            uint32_t ah[4][4], al[4][4];
#pragma unroll
            for (int mt = 0; mt < 4; ++mt) {
                uint32_t ca = (uint32_t)(2 * s) + cAsel;
                uint32_t ad = stg + aoff[mt] + ((ca ^ asw[mt]) << 4);
                ldsm4(ah[mt], ad + OFF_AH);
                ldsm4(al[mt], ad + OFF_AL);
            }
            uint32_t bh[4][2], bl[4][2];
#pragma unroll
            for (int jj = 0; jj < 2; ++jj) {
                uint32_t cb = (uint32_t)(2 * s) + cBsel;
                uint32_t bd = stg + boff[jj] + ((cb ^ bsw[jj]) << 4);
                uint32_t rh[4], rl[4];
                ldsm4(rh, bd + OFF_BH);
                ldsm4(rl, bd + OFF_BL);
                bh[2 * jj][0] = rh[0]; bh[2 * jj][1] = rh[1];
                bh[2 * jj + 1][0] = rh[2]; bh[2 * jj + 1][1] = rh[3];
                bl[2 * jj][0] = rl[0]; bl[2 * jj][1] = rl[1];
                bl[2 * jj + 1][0] = rl[2]; bl[2 * jj + 1][1] = rl[3];
            }
#pragma unroll
            for (int mt = 0; mt < 4; ++mt)
#pragma unroll
                for (int nt = 0; nt < 4; ++nt) {
                    mma16816(acc[mt][nt], ah[mt], bh[nt]);
                    mma16816(acc[mt][nt], ah[mt], bl[nt]);
                    mma16816(acc[mt][nt], al[mt], bh[nt]);
                }
        }
    }

    // epilogue: + bias, direct f32x2 stores
    __syncthreads();
    const float* sbias = reinterpret_cast<const float*>(smem + SM_BIAS);
#pragma unroll
    for (int mt = 0; mt < 4; ++mt) {
#pragma unroll
        for (int nt = 0; nt < 4; ++nt) {
            int row = tm * BM + wm * 64 + mt * 16 + (lane >> 2);
            int cl = wn * 32 + nt * 8 + 2 * (lane & 3);
            float b0 = sbias[cl], b1 = sbias[cl + 1];
            float* p0 = out + (size_t)row * DIM + tn * BN + cl;
            float* p1 = p0 + 8 * DIM;
            float2 v0 = make_float2(acc[mt][nt][0] + b0, acc[mt][nt][1] + b1);
            float2 v1 = make_float2(acc[mt][nt][2] + b0, acc[mt][nt][3] + b1);
            *reinterpret_cast<float2*>(p0) = v0;
            *reinterpret_cast<float2*>(p1) = v1;
        }
    }
}

// ---------------------------------------------------------------------------
// Launch
// ---------------------------------------------------------------------------
extern "C" void kernel_launch(void* const* d_in, const int* in_sizes, int n_in,
                              void* d_out, int out_size) {
    const float* x = (const float*)d_in[0];
    const float* W = (const float*)d_in[1];
    const float* b = (const float*)d_in[2];
    float* out = (float*)d_out;

    split_kernel<<<16384, 256>>>(x, 0);
    split_kernel<<<16384, 256>>>(W, 1);

    static int configured = 0;
    cudaFuncSetAttribute(gemm_kernel, cudaFuncAttributeMaxDynamicSharedMemorySize,
                         SMEM_TOTAL);
    (void)configured;
    gemm_kernel<<<(DIM / BM) * (DIM / BN), THREADS, SMEM_TOTAL>>>(b, out);
}